// round 12
// baseline (speedup 1.0000x reference)
#include <cuda_runtime.h>

#define NBOX 10647
#define NCLS 80
#define MAXDET 300
#define SCORE_THR 0.3f
#define IOU_THR 0.45f
#define INPUT_SZ 416.0
#define MAXPER 384               // per-class bucket capacity (expected 93±10)
#define NMAX 256                 // matrix-path cap per class
#define WMAX 8                   // fixed suppression-row stride (words)
#define CCAP 1024                // candidate cap (expected ~310)
#define NBIN 2048
#define GRID 80                  // 1 block/SM, all co-resident (<= 148 SMs)
#define NTHR 512

// Per-class buckets (decode phase -> nms phase).
__device__ float4             g_bbox[NCLS * MAXPER];
__device__ unsigned long long g_bkey[NCLS * MAXPER];
__device__ int                g_cnt[NCLS];        // reset by nms block c each run

// Select state (all reset by last block each run; g_done auto-wraps).
__device__ unsigned int       g_hist[NBIN];
__device__ unsigned long long g_ckey[CCAP];
__device__ unsigned char      g_ccls[CCAP];
__device__ int                g_ccnt;
__device__ unsigned int       g_bar1, g_bar2;
__device__ unsigned int       g_done;

// ---------------------------------------------------------------------------
// Single fused launch, 80 blocks x 512 thr, ~29KB dsmem, 1 block/SM ->
// all co-resident in wave 1 (spin barriers deadlock-free).
//  A) decode: THREAD per box (85 batched LDGs, in-register argmax) -> buckets.
//     Blocks 21..79 zero `out` (they hold no boxes: 21*512 > NBOX... they do
//     hold boxes only for c*512 < NBOX, i.e. c <= 20).
//  B) barrier-1 (80 arrivals).
//  C) block c = class c: counting sort desc (keys unique), sorted-box cache,
//     suppression bitmask matrix (mul-form IoU), register serial scan
//     (== greedy NMS; suppression is class-local). Picks histogrammed.
//  D) barrier-2 (80); every block computes threshold bin T (identical),
//     appends its picks with bin >= T (upward-closed set -> rank among
//     candidates == global rank).
//  E) last block (g_done): C^2 rank over ~310 candidates, scatter, reset.
// ---------------------------------------------------------------------------
#define OFF_SKEY2 (MAXPER * 8)                    // 3072
#define OFF_SBOX  (OFF_SKEY2 + MAXPER * 8)        // 6144
#define OFF_SBOXS (OFF_SBOX + MAXPER * 16)        // 12288 (sorted-order boxes)
#define OFF_SROW  (OFF_SBOXS + MAXPER * 16)       // 18432 (16B aligned)
#define OFF_SPICK (OFF_SROW + NMAX * WMAX * 4)    // 26624
#define DSMEM_BYTES (OFF_SPICK + MAXDET * 8)      // 29024
#define OFF_CKEY  8192                            // phase E overlays dead sbox
#define OFF_CCLS  (OFF_CKEY + CCAP * 8)           // 16384 (dead sboxs region)

extern __shared__ unsigned char dsm[];

__global__ __launch_bounds__(NTHR, 1) void yolo_fused_kernel(
        const float* __restrict__ pred,
        const int* __restrict__ p_oh,
        const int* __restrict__ p_ow,
        float* __restrict__ out) {
    __shared__ float s_r, s_dw, s_dh, s_xmax, s_ymax;
    __shared__ int  s_npick, s_T;
    __shared__ bool amLast;
    __shared__ unsigned int super[64];

    int tid  = threadIdx.x;
    int lane = tid & 31;
    int c    = blockIdx.x;

    // ---- phase A: decode (one thread per box) ----
    if (tid == 0) {
        int oh = p_oh[0], ow = p_ow[0];
        double rw = INPUT_SZ / (double)ow;
        double rh = INPUT_SZ / (double)oh;
        double rr = rw < rh ? rw : rh;
        s_r    = (float)rr;
        s_dw   = (float)((INPUT_SZ - rr * (double)ow) * 0.5);
        s_dh   = (float)((INPUT_SZ - rr * (double)oh) * 0.5);
        s_xmax = (float)(ow - 1);
        s_ymax = (float)(oh - 1);
    }
    __syncthreads();

    int box = c * NTHR + tid;
    if (box < NBOX) {
        const float* p = pred + box * 85;

        // Serial argmax, strict > keeps the earliest class (jnp.argmax).
        float best = p[5];
        int bestc = 0;
        #pragma unroll 16
        for (int cl = 1; cl < NCLS; cl++) {
            float v = p[5 + cl];
            if (v > best) { best = v; bestc = cl; }
        }

        float r = s_r, dw = s_dw, dh = s_dh;
        float cx = p[0], cy = p[1], w = p[2], h = p[3], conf = p[4];
        float x1 = (cx - w * 0.5f - dw) / r;
        float y1 = (cy - h * 0.5f - dh) / r;
        float x2 = (cx + w * 0.5f - dw) / r;
        float y2 = (cy + h * 0.5f - dh) / r;
        x1 = fmaxf(x1, 0.0f);
        y1 = fmaxf(y1, 0.0f);
        x2 = fminf(x2, s_xmax);
        y2 = fminf(y2, s_ymax);
        if (x1 > x2 || y1 > y2) { x1 = y1 = x2 = y2 = 0.0f; }

        float area  = (x2 - x1) * (y2 - y1);
        float score = conf * best;
        if (area > 0.0f && score > SCORE_THR) {
            int slot = atomicAdd(&g_cnt[bestc], 1);
            if (slot < MAXPER) {
                g_bbox[bestc * MAXPER + slot] = make_float4(x1, y1, x2, y2);
                // key: score (desc) > orig idx (asc via NBOX-box) > slot (10b).
                g_bkey[bestc * MAXPER + slot] =
                    ((unsigned long long)__float_as_uint(score) << 32) |
                    ((unsigned long long)(NBOX - box) << 10) |
                    (unsigned long long)(slot & 1023);
            }
        }
    }

    // Boxless blocks (c >= 21) zero `out` before arriving at barrier-1.
    if (c * NTHR >= NBOX) {
        for (int j = (c - 21) * NTHR + tid; j < MAXDET * 6; j += 59 * NTHR)
            out[j] = 0.0f;
    }

    // ---- phase B: barrier-1 (80 arrivals) ----
    __syncthreads();
    __threadfence();
    if (tid == 0) {
        atomicAdd(&g_bar1, 1u);
        while (*(volatile unsigned int*)&g_bar1 < GRID) __nanosleep(32);
    }
    __syncthreads();

    // ---- phase C: per-class NMS (block c = class c) ----
    unsigned long long* skey  = (unsigned long long*)dsm;
    unsigned long long* skey2 = (unsigned long long*)(dsm + OFF_SKEY2);
    float4*             sbox  = (float4*)(dsm + OFF_SBOX);
    float4*             sboxs = (float4*)(dsm + OFF_SBOXS);
    unsigned int*       srow  = (unsigned int*)(dsm + OFF_SROW);
    unsigned long long* spick = (unsigned long long*)(dsm + OFF_SPICK);

    int n = g_cnt[c];
    if (n > MAXPER) n = MAXPER;
    if (tid == 0) {
        g_cnt[c] = 0;                       // restore invariant for next replay
        s_npick = 0;
    }
    __syncthreads();

    if (n > 0) {
        for (int j = tid; j < n; j += NTHR) {
            skey[j] = g_bkey[c * MAXPER + j];
            sbox[j] = g_bbox[c * MAXPER + j];
        }
        __syncthreads();

        // Counting sort descending: keys unique -> ranks unique in [0,n).
        for (int i = tid; i < n; i += NTHR) {
            unsigned long long ki = skey[i];
            int rank = 0;
            #pragma unroll 4
            for (int j = 0; j < n; j++) rank += (skey[j] > ki);
            skey2[rank] = ki;
        }
        __syncthreads();
        // Sorted-order box cache (removes indirection from the O(n^2) loop).
        for (int i = tid; i < n; i += NTHR)
            sboxs[i] = sbox[(int)(skey2[i] & 1023u)];
        __syncthreads();

        if (n <= NMAX) {
            // Suppression matrix, fixed stride WMAX: bit j of row i (j<i).
            int W = (n + 31) >> 5;
            for (int t = tid; t < n * W; t += NTHR) {
                int i = t / W, w = t % W;
                float4 bi = sboxs[i];
                float ai = (bi.z - bi.x) * (bi.w - bi.y);
                unsigned int bits = 0;
                int jend = min(i, (w + 1) * 32);
                for (int j = w * 32; j < jend; j++) {
                    float4 bj = sboxs[j];
                    float iw = fminf(bi.z, bj.z) - fmaxf(bi.x, bj.x);
                    float ih = fminf(bi.w, bj.w) - fmaxf(bi.y, bj.y);
                    iw = fmaxf(iw, 0.0f);
                    ih = fmaxf(ih, 0.0f);
                    float inter = iw * ih;
                    float uni = ai + (bj.z - bj.x) * (bj.w - bj.y) - inter;
                    // uni > 0 (bucketed boxes have area > 0): mul == div form
                    if (inter > IOU_THR * uni) bits |= 1u << (j & 31);
                }
                srow[i * WMAX + w] = bits;
            }
            __syncthreads();
            // Serial scan, kept-mask in registers; rows as 2x uint4 LDS.128.
            if (tid == 0) {
                const uint4* rowp = (const uint4*)(dsm + OFF_SROW);
                uint4 k0 = make_uint4(0, 0, 0, 0);
                uint4 k1 = make_uint4(0, 0, 0, 0);
                int npick = 0;
                for (int i = 0; i < n; i++) {
                    uint4 r0 = rowp[i * 2];
                    uint4 r1 = rowp[i * 2 + 1];
                    unsigned int sup =
                        (r0.x & k0.x) | (r0.y & k0.y) | (r0.z & k0.z) | (r0.w & k0.w) |
                        (r1.x & k1.x) | (r1.y & k1.y) | (r1.z & k1.z) | (r1.w & k1.w);
                    if (!sup) {
                        unsigned int b = 1u << (i & 31);
                        switch (i >> 5) {
                            case 0: k0.x |= b; break;
                            case 1: k0.y |= b; break;
                            case 2: k0.z |= b; break;
                            case 3: k0.w |= b; break;
                            case 4: k1.x |= b; break;
                            case 5: k1.y |= b; break;
                            case 6: k1.z |= b; break;
                            default: k1.w |= b; break;
                        }
                        spick[npick++] = skey2[i];
                        if (npick == MAXDET) break;
                    }
                }
                s_npick = npick;
            }
        } else {
            // Fallback (NMAX < n <= MAXPER, statistically untaken): warp-0 scan.
            if (tid < 32) {
                unsigned short* skept = (unsigned short*)srow;
                int m2 = 0, npick = 0;
                for (int i = 0; i < n && npick < MAXDET; i++) {
                    float4 b = sboxs[i];
                    float ab = (b.z - b.x) * (b.w - b.y);
                    bool sup = false;
                    for (int j0 = 0; j0 < m2; j0 += 32) {
                        bool pr = false;
                        int j = j0 + lane;
                        if (j < m2) {
                            float4 kb = sboxs[skept[j]];
                            float iw = fminf(b.z, kb.z) - fmaxf(b.x, kb.x);
                            float ih = fminf(b.w, kb.w) - fmaxf(b.y, kb.y);
                            iw = fmaxf(iw, 0.0f);
                            ih = fmaxf(ih, 0.0f);
                            float inter = iw * ih;
                            float uni = ab + (kb.z - kb.x) * (kb.w - kb.y) - inter;
                            pr = (inter > IOU_THR * uni);
                        }
                        if (__any_sync(0xffffffffu, pr)) { sup = true; break; }
                    }
                    if (!sup) {
                        if (lane == 0) {
                            skept[m2] = (unsigned short)i;   // sorted index
                            spick[npick] = skey2[i];
                        }
                        __syncwarp();
                        m2++; npick++;
                    }
                }
                if (lane == 0) s_npick = npick;
            }
        }
        __syncthreads();

        // Histogram this block's picks (scores in (0.3,1] -> bin in [0,1848)).
        int npick = s_npick;
        for (int j = tid; j < npick; j += NTHR) {
            unsigned int sb2 = (unsigned int)(spick[j] >> 32);
            atomicAdd(&g_hist[(sb2 - 0x3E990000u) >> 13], 1u);
        }
    }

    // ---- phase D: barrier-2, per-block threshold, candidate append ----
    __syncthreads();
    __threadfence();
    if (tid == 0) {
        atomicAdd(&g_bar2, 1u);
        while (*(volatile unsigned int*)&g_bar2 < GRID) __nanosleep(32);
    }
    __syncthreads();

    // Every block computes the same T from the completed global histogram.
    unsigned int* sh = (unsigned int*)dsm;          // overlays dead skey/skey2
    for (int j = tid; j < NBIN; j += NTHR) sh[j] = g_hist[j];
    __syncthreads();
    if (tid < 64) {
        unsigned int s = 0;
        for (int w = 0; w < 32; w++) s += sh[tid * 32 + w];
        super[tid] = s;
    }
    __syncthreads();
    if (tid == 0) {
        int cum = 0, T = 0;
        int sb2 = 63;
        for (; sb2 >= 0; sb2--) {
            if (cum + (int)super[sb2] >= MAXDET) break;
            cum += (int)super[sb2];
        }
        if (sb2 >= 0) {
            int b = sb2 * 32 + 31;
            for (; b >= sb2 * 32; b--) {
                cum += (int)sh[b];
                if (cum >= MAXDET) break;
            }
            T = (b < sb2 * 32) ? sb2 * 32 : b;
        }
        s_T = T;                            // T==0 when total<300: all picks
    }
    __syncthreads();

    int T = s_T;
    int npick = s_npick;
    for (int j = tid; j < npick; j += NTHR) {
        unsigned long long k = spick[j];
        int b = (int)(((unsigned int)(k >> 32) - 0x3E990000u) >> 13);
        if (b >= T) {
            int idx = atomicAdd(&g_ccnt, 1);
            if (idx < CCAP) { g_ckey[idx] = k; g_ccls[idx] = (unsigned char)c; }
        }
    }

    // ---- phase E: last block ranks candidates and scatters ----
    __threadfence();
    if (tid == 0)
        amLast = (atomicInc(&g_done, GRID - 1) == GRID - 1);  // auto-resets
    __syncthreads();
    if (!amLast) return;

    unsigned long long* ckey = (unsigned long long*)(dsm + OFF_CKEY);
    unsigned char*      ccls = (unsigned char*)(dsm + OFF_CCLS);
    __shared__ int s_C;

    if (tid == 0) {
        int C = g_ccnt;
        s_C = (C > CCAP) ? CCAP : C;
        g_ccnt = 0;                         // restore invariants
        g_bar1 = 0;
        g_bar2 = 0;
    }
    for (int j = tid; j < NBIN; j += NTHR) g_hist[j] = 0;
    __syncthreads();

    int C = s_C;
    for (int j = tid; j < C; j += NTHR) {
        ckey[j] = g_ckey[j];
        ccls[j] = g_ccls[j];
    }
    __syncthreads();

    for (int t = tid; t < C; t += NTHR) {
        unsigned long long mk = ckey[t];
        int rank = 0;
        for (int j = 0; j < C; j++) rank += (ckey[j] > mk);
        if (rank < MAXDET) {
            int cls  = ccls[t];
            int slot = (int)(mk & 1023u);
            float4 b = g_bbox[cls * MAXPER + slot];
            float* row = out + rank * 6;
            row[0] = b.x; row[1] = b.y; row[2] = b.z; row[3] = b.w;
            row[4] = __uint_as_float((unsigned int)(mk >> 32));
            row[5] = (float)cls;
        }
    }
}

// ---------------------------------------------------------------------------
extern "C" void kernel_launch(void* const* d_in, const int* in_sizes, int n_in,
                              void* d_out, int out_size) {
    const float* pred = (const float*)d_in[0];
    const int*   oh   = (const int*)d_in[1];
    const int*   ow   = (const int*)d_in[2];
    float*       out  = (float*)d_out;

    cudaFuncSetAttribute(yolo_fused_kernel,
                         cudaFuncAttributeMaxDynamicSharedMemorySize,
                         DSMEM_BYTES);

    yolo_fused_kernel<<<GRID, NTHR, DSMEM_BYTES>>>(pred, oh, ow, out);
}

// round 16
// speedup vs baseline: 1.0855x; 1.0855x over previous
#include <cuda_runtime.h>

#define NBOX 10647
#define NCLS 80
#define MAXDET 300
#define SCORE_THR 0.3f
#define IOU_THR 0.45f
#define INPUT_SZ 416.0
#define MAXPER 384               // per-class bucket capacity (expected 93±10)
#define NMAX 256                 // matrix-path cap per class
#define WMAX 8                   // fixed suppression-row stride (words)
#define CCAP 1024                // candidate cap (expected ~310)
#define NBIN 2048
#define GRID 288                 // <= 2 blocks/SM x 148 SMs: all co-resident
#define NWARP 16
#define GWARPS (GRID * NWARP)    // 4608 decode warps

// Per-class buckets (decode phase -> nms phase).
__device__ float4             g_bbox[NCLS * MAXPER];
__device__ unsigned long long g_bkey[NCLS * MAXPER];
__device__ int                g_cnt[NCLS];        // reset by nms block c each run

// Select state (all reset by last block each run; g_done auto-wraps).
__device__ unsigned int       g_hist[NBIN];
__device__ unsigned long long g_ckey[CCAP];
__device__ unsigned char      g_ccls[CCAP];
__device__ int                g_ccnt;
__device__ unsigned int       g_bar1, g_bar2;
__device__ unsigned int       g_done;

// ---------------------------------------------------------------------------
// Single fused launch (R11-validated, 39.4us) + R14 race fix in phase E.
// 288 blocks x 512 thr, ~29KB dsmem, 2 blocks/SM -> all co-resident in
// wave 1 (spin barriers deadlock-free; validated R8/R10/R11/R12).
//  A) decode: warp/box (REDUX argmax) -> per-class buckets. Blocks >= NCLS
//     zero `out`, arrive at barrier-1, exit.
//  B) barrier-1 (288 arrivals; only NMS blocks spin).
//  C) block c = class c: counting sort desc (keys unique), sorted-box cache,
//     suppression bitmask matrix (mul-form IoU), register serial scan
//     (== greedy NMS; suppression is class-local). Picks histogrammed.
//  D) barrier-2 (80); every block computes threshold bin T (identical),
//     appends its picks with bin >= T (upward-closed -> rank among
//     candidates == global rank).
//  E) RACE FIX: __syncthreads() before the g_done arrival so all of a
//     block's appends complete (and are fenced by every thread) before the
//     block is counted done. Last block: C^2 rank, scatter, reset.
// ---------------------------------------------------------------------------
#define OFF_SKEY2 (MAXPER * 8)                    // 3072
#define OFF_SBOX  (OFF_SKEY2 + MAXPER * 8)        // 6144
#define OFF_SBOXS (OFF_SBOX + MAXPER * 16)        // 12288 (sorted-order boxes)
#define OFF_SROW  (OFF_SBOXS + MAXPER * 16)       // 18432 (16B aligned)
#define OFF_SPICK (OFF_SROW + NMAX * WMAX * 4)    // 26624
#define DSMEM_BYTES (OFF_SPICK + MAXDET * 8)      // 29024
#define OFF_CKEY  8192                            // phase E overlays dead sbox
#define OFF_CCLS  (OFF_CKEY + CCAP * 8)           // 16384 (dead sboxs region)

extern __shared__ unsigned char dsm[];

__global__ __launch_bounds__(512, 2) void yolo_fused_kernel(
        const float* __restrict__ pred,
        const int* __restrict__ p_oh,
        const int* __restrict__ p_ow,
        float* __restrict__ out) {
    __shared__ float s_r, s_dw, s_dh, s_xmax, s_ymax;
    __shared__ int  s_npick, s_T;
    __shared__ bool amLast;
    __shared__ unsigned int super[64];

    int tid  = threadIdx.x;
    int wid  = tid >> 5;
    int lane = tid & 31;
    int c    = blockIdx.x;

    // ---- phase A: decode (warp per box, full chip) ----
    if (tid == 0) {
        int oh = p_oh[0], ow = p_ow[0];
        double rw = INPUT_SZ / (double)ow;
        double rh = INPUT_SZ / (double)oh;
        double rr = rw < rh ? rw : rh;
        s_r    = (float)rr;
        s_dw   = (float)((INPUT_SZ - rr * (double)ow) * 0.5);
        s_dh   = (float)((INPUT_SZ - rr * (double)oh) * 0.5);
        s_xmax = (float)(ow - 1);
        s_ymax = (float)(oh - 1);
    }
    __syncthreads();

    for (int box = c * NWARP + wid; box < NBOX; box += GWARPS) {
        const float* p = pred + box * 85;

        // Per-lane argmax keeps the EARLIEST class achieving the lane max.
        float best = -1.0f;
        int bestc = 0;
        for (int cl = lane; cl < NCLS; cl += 32) {
            float v = p[5 + cl];
            if (v > best) { best = v; bestc = cl; }
        }
        // Cross-lane: max score bits (non-negative floats monotone), then min
        // class among lanes holding the max -> exact jnp.argmax semantics.
        unsigned int sb = __float_as_uint(best);
        unsigned int m  = __reduce_max_sync(0xffffffffu, sb);
        unsigned int cand = (sb == m) ? (unsigned int)bestc : 0xffffffffu;
        unsigned int minc = __reduce_min_sync(0xffffffffu, cand);
        if (lane) continue;
        best  = __uint_as_float(m);
        bestc = (int)minc;

        float r = s_r, dw = s_dw, dh = s_dh;
        float cx = p[0], cy = p[1], w = p[2], h = p[3], conf = p[4];
        float x1 = (cx - w * 0.5f - dw) / r;
        float y1 = (cy - h * 0.5f - dh) / r;
        float x2 = (cx + w * 0.5f - dw) / r;
        float y2 = (cy + h * 0.5f - dh) / r;
        x1 = fmaxf(x1, 0.0f);
        y1 = fmaxf(y1, 0.0f);
        x2 = fminf(x2, s_xmax);
        y2 = fminf(y2, s_ymax);
        if (x1 > x2 || y1 > y2) { x1 = y1 = x2 = y2 = 0.0f; }

        float area  = (x2 - x1) * (y2 - y1);
        float score = conf * best;
        if (!(area > 0.0f && score > SCORE_THR)) continue;

        int slot = atomicAdd(&g_cnt[bestc], 1);
        if (slot < MAXPER) {
            g_bbox[bestc * MAXPER + slot] = make_float4(x1, y1, x2, y2);
            // key: score (desc) > orig index (asc via NBOX-box) > slot (10b).
            g_bkey[bestc * MAXPER + slot] =
                ((unsigned long long)__float_as_uint(score) << 32) |
                ((unsigned long long)(NBOX - box) << 10) |
                (unsigned long long)(slot & 1023);
        }
    }

    // Non-NMS blocks zero `out` BEFORE arriving at barrier-1.
    if (c >= NCLS) {
        for (int j = (c - NCLS) * 512 + tid; j < MAXDET * 6; j += 208 * 512)
            out[j] = 0.0f;
    }

    // ---- phase B: barrier-1 ----
    __syncthreads();
    __threadfence();
    if (tid == 0) {
        atomicAdd(&g_bar1, 1u);
        if (c < NCLS)
            while (*(volatile unsigned int*)&g_bar1 < GRID) __nanosleep(32);
    }
    __syncthreads();
    if (c >= NCLS) return;

    // ---- phase C: per-class NMS (block c = class c) ----
    unsigned long long* skey  = (unsigned long long*)dsm;
    unsigned long long* skey2 = (unsigned long long*)(dsm + OFF_SKEY2);
    float4*             sbox  = (float4*)(dsm + OFF_SBOX);
    float4*             sboxs = (float4*)(dsm + OFF_SBOXS);
    unsigned int*       srow  = (unsigned int*)(dsm + OFF_SROW);
    unsigned long long* spick = (unsigned long long*)(dsm + OFF_SPICK);

    int n = g_cnt[c];
    if (n > MAXPER) n = MAXPER;
    if (tid == 0) {
        g_cnt[c] = 0;                       // restore invariant for next replay
        s_npick = 0;
    }
    __syncthreads();

    if (n > 0) {
        for (int j = tid; j < n; j += 512) {
            skey[j] = g_bkey[c * MAXPER + j];
            sbox[j] = g_bbox[c * MAXPER + j];
        }
        __syncthreads();

        // Counting sort descending: keys unique -> ranks unique in [0,n).
        for (int i = tid; i < n; i += 512) {
            unsigned long long ki = skey[i];
            int rank = 0;
            #pragma unroll 4
            for (int j = 0; j < n; j++) rank += (skey[j] > ki);
            skey2[rank] = ki;
        }
        __syncthreads();
        // Sorted-order box cache (removes indirection from the O(n^2) loop).
        for (int i = tid; i < n; i += 512)
            sboxs[i] = sbox[(int)(skey2[i] & 1023u)];
        __syncthreads();

        if (n <= NMAX) {
            // Suppression matrix, fixed stride WMAX: bit j of row i (j<i).
            int W = (n + 31) >> 5;
            for (int t = tid; t < n * W; t += 512) {
                int i = t / W, w = t % W;
                float4 bi = sboxs[i];
                float ai = (bi.z - bi.x) * (bi.w - bi.y);
                unsigned int bits = 0;
                int jend = min(i, (w + 1) * 32);
                for (int j = w * 32; j < jend; j++) {
                    float4 bj = sboxs[j];
                    float iw = fminf(bi.z, bj.z) - fmaxf(bi.x, bj.x);
                    float ih = fminf(bi.w, bj.w) - fmaxf(bi.y, bj.y);
                    iw = fmaxf(iw, 0.0f);
                    ih = fmaxf(ih, 0.0f);
                    float inter = iw * ih;
                    float uni = ai + (bj.z - bj.x) * (bj.w - bj.y) - inter;
                    // uni > 0 (bucketed boxes have area > 0): mul == div form
                    if (inter > IOU_THR * uni) bits |= 1u << (j & 31);
                }
                srow[i * WMAX + w] = bits;
            }
            __syncthreads();
            // Serial scan, kept-mask in registers; rows as 2x uint4 LDS.128.
            if (tid == 0) {
                const uint4* rowp = (const uint4*)(dsm + OFF_SROW);
                uint4 k0 = make_uint4(0, 0, 0, 0);
                uint4 k1 = make_uint4(0, 0, 0, 0);
                int npick = 0;
                for (int i = 0; i < n; i++) {
                    uint4 r0 = rowp[i * 2];
                    uint4 r1 = rowp[i * 2 + 1];
                    unsigned int sup =
                        (r0.x & k0.x) | (r0.y & k0.y) | (r0.z & k0.z) | (r0.w & k0.w) |
                        (r1.x & k1.x) | (r1.y & k1.y) | (r1.z & k1.z) | (r1.w & k1.w);
                    if (!sup) {
                        unsigned int b = 1u << (i & 31);
                        switch (i >> 5) {
                            case 0: k0.x |= b; break;
                            case 1: k0.y |= b; break;
                            case 2: k0.z |= b; break;
                            case 3: k0.w |= b; break;
                            case 4: k1.x |= b; break;
                            case 5: k1.y |= b; break;
                            case 6: k1.z |= b; break;
                            default: k1.w |= b; break;
                        }
                        spick[npick++] = skey2[i];
                        if (npick == MAXDET) break;
                    }
                }
                s_npick = npick;
            }
        } else {
            // Fallback (NMAX < n <= MAXPER, statistically untaken): warp-0 scan.
            if (tid < 32) {
                unsigned short* skept = (unsigned short*)srow;
                int m2 = 0, npick = 0;
                for (int i = 0; i < n && npick < MAXDET; i++) {
                    float4 b = sboxs[i];
                    float ab = (b.z - b.x) * (b.w - b.y);
                    bool sup = false;
                    for (int j0 = 0; j0 < m2; j0 += 32) {
                        bool pr = false;
                        int j = j0 + lane;
                        if (j < m2) {
                            float4 kb = sboxs[skept[j]];
                            float iw = fminf(b.z, kb.z) - fmaxf(b.x, kb.x);
                            float ih = fminf(b.w, kb.w) - fmaxf(b.y, kb.y);
                            iw = fmaxf(iw, 0.0f);
                            ih = fmaxf(ih, 0.0f);
                            float inter = iw * ih;
                            float uni = ab + (kb.z - kb.x) * (kb.w - kb.y) - inter;
                            pr = (inter > IOU_THR * uni);
                        }
                        if (__any_sync(0xffffffffu, pr)) { sup = true; break; }
                    }
                    if (!sup) {
                        if (lane == 0) {
                            skept[m2] = (unsigned short)i;   // sorted index
                            spick[npick] = skey2[i];
                        }
                        __syncwarp();
                        m2++; npick++;
                    }
                }
                if (lane == 0) s_npick = npick;
            }
        }
        __syncthreads();

        // Histogram this block's picks (scores in (0.3,1] -> bin in [0,1848)).
        int npick = s_npick;
        for (int j = tid; j < npick; j += 512) {
            unsigned int sb2 = (unsigned int)(spick[j] >> 32);
            atomicAdd(&g_hist[(sb2 - 0x3E990000u) >> 13], 1u);
        }
    }

    // ---- phase D: barrier-2, per-block threshold, candidate append ----
    __syncthreads();
    __threadfence();
    if (tid == 0) {
        atomicAdd(&g_bar2, 1u);
        while (*(volatile unsigned int*)&g_bar2 < NCLS) __nanosleep(32);
    }
    __syncthreads();

    // Every block computes the same T from the completed global histogram.
    unsigned int* sh = (unsigned int*)dsm;          // overlays dead skey/skey2
    for (int j = tid; j < NBIN; j += 512) sh[j] = g_hist[j];
    __syncthreads();
    if (tid < 64) {
        unsigned int s = 0;
        for (int w = 0; w < 32; w++) s += sh[tid * 32 + w];
        super[tid] = s;
    }
    __syncthreads();
    if (tid == 0) {
        int cum = 0, T = 0;
        int sb2 = 63;
        for (; sb2 >= 0; sb2--) {
            if (cum + (int)super[sb2] >= MAXDET) break;
            cum += (int)super[sb2];
        }
        if (sb2 >= 0) {
            int b = sb2 * 32 + 31;
            for (; b >= sb2 * 32; b--) {
                cum += (int)sh[b];
                if (cum >= MAXDET) break;
            }
            T = (b < sb2 * 32) ? sb2 * 32 : b;
        }
        s_T = T;                            // T==0 when total<300: all picks
    }
    __syncthreads();

    int T = s_T;
    int npick = s_npick;
    for (int j = tid; j < npick; j += 512) {
        unsigned long long k = spick[j];
        int b = (int)(((unsigned int)(k >> 32) - 0x3E990000u) >> 13);
        if (b >= T) {
            int idx = atomicAdd(&g_ccnt, 1);
            if (idx < CCAP) { g_ckey[idx] = k; g_ccls[idx] = (unsigned char)c; }
        }
    }

    // ---- phase E: last block ranks candidates and scatters ----
    // RACE FIX (R14 lesson): all threads of this block must finish their
    // appends BEFORE the block arrives on g_done; every thread fences so the
    // appended data+count are globally visible before the arrival.
    __syncthreads();
    __threadfence();
    if (tid == 0)
        amLast = (atomicInc(&g_done, NCLS - 1) == NCLS - 1);  // auto-resets
    __syncthreads();
    if (!amLast) return;

    unsigned long long* ckey = (unsigned long long*)(dsm + OFF_CKEY);
    unsigned char*      ccls = (unsigned char*)(dsm + OFF_CCLS);
    __shared__ int s_C;

    if (tid == 0) {
        int C = g_ccnt;
        s_C = (C > CCAP) ? CCAP : C;
        g_ccnt = 0;                         // restore invariants
        g_bar1 = 0;
        g_bar2 = 0;
    }
    for (int j = tid; j < NBIN; j += 512) g_hist[j] = 0;
    __syncthreads();

    int C = s_C;
    for (int j = tid; j < C; j += 512) {
        ckey[j] = g_ckey[j];
        ccls[j] = g_ccls[j];
    }
    __syncthreads();

    for (int t = tid; t < C; t += 512) {
        unsigned long long mk = ckey[t];
        int rank = 0;
        for (int j = 0; j < C; j++) rank += (ckey[j] > mk);
        if (rank < MAXDET) {
            int cls  = ccls[t];
            int slot = (int)(mk & 1023u);
            float4 b = g_bbox[cls * MAXPER + slot];
            float* row = out + rank * 6;
            row[0] = b.x; row[1] = b.y; row[2] = b.z; row[3] = b.w;
            row[4] = __uint_as_float((unsigned int)(mk >> 32));
            row[5] = (float)cls;
        }
    }
}

// ---------------------------------------------------------------------------
extern "C" void kernel_launch(void* const* d_in, const int* in_sizes, int n_in,
                              void* d_out, int out_size) {
    const float* pred = (const float*)d_in[0];
    const int*   oh   = (const int*)d_in[1];
    const int*   ow   = (const int*)d_in[2];
    float*       out  = (float*)d_out;

    cudaFuncSetAttribute(yolo_fused_kernel,
                         cudaFuncAttributeMaxDynamicSharedMemorySize,
                         DSMEM_BYTES);

    yolo_fused_kernel<<<GRID, 512, DSMEM_BYTES>>>(pred, oh, ow, out);
}

// round 17
// speedup vs baseline: 1.1446x; 1.0544x over previous
#include <cuda_runtime.h>

#define NBOX 10647
#define NCLS 80
#define MAXDET 300
#define SCORE_THR 0.3f
#define IOU_THR 0.45f
#define INPUT_SZ 416.0
#define MAXPER 384               // per-class bucket capacity (expected 93±10)
#define NMAX 256                 // matrix-path cap per class
#define WMAX 8                   // fixed suppression-row stride (words)
#define CCAP 1024                // candidate cap (expected ~310)
#define NBIN 2048
#define GRID 288                 // <= 2 blocks/SM x 148 SMs: all co-resident
#define NWARP 16
#define GWARPS (GRID * NWARP)    // 4608 decode warps

// Per-class buckets (decode phase -> nms phase).
__device__ float4             g_bbox[NCLS * MAXPER];
__device__ unsigned long long g_bkey[NCLS * MAXPER];
__device__ int                g_cnt[NCLS];        // reset by nms block c each run

// Select state (all reset by last block each run; g_done auto-wraps).
__device__ unsigned int       g_hist[NBIN];
__device__ unsigned long long g_ckey[CCAP];
__device__ unsigned char      g_ccls[CCAP];
__device__ int                g_ccnt;
__device__ unsigned int       g_bar1, g_bar2;
__device__ unsigned int       g_done;

// ---------------------------------------------------------------------------
// Single fused launch (R16-validated base + serial-chain trims).
// 288 blocks x 512 thr, ~29KB dsmem, 2 blocks/SM -> all co-resident wave 1.
//  A) decode: warp/box (REDUX argmax) -> per-class buckets. Blocks >= NCLS
//     zero `out`, arrive at barrier-1, exit.
//  B) barrier-1 (288 arrivals; only NMS blocks spin).
//  C) block c = class c: counting sort desc (box permute fused), suppression
//     bitmask matrix (mul-form IoU), PIPELINED register serial scan
//     (== greedy NMS; suppression is class-local). Picks histogrammed.
//  D) barrier-2 (80); every block computes threshold bin T (identical),
//     appends picks with bin >= T (upward-closed -> rank among candidates
//     == global rank).
//  E) all-appends-done __syncthreads + fence before g_done arrival (R14 race
//     fix). Last block: C^2 rank (unrolled), scatter, reset.
// ---------------------------------------------------------------------------
#define OFF_SKEY2 (MAXPER * 8)                    // 3072
#define OFF_SBOX  (OFF_SKEY2 + MAXPER * 8)        // 6144
#define OFF_SBOXS (OFF_SBOX + MAXPER * 16)        // 12288 (sorted-order boxes)
#define OFF_SROW  (OFF_SBOXS + MAXPER * 16)       // 18432 (16B aligned)
#define OFF_SPICK (OFF_SROW + NMAX * WMAX * 4)    // 26624
#define DSMEM_BYTES (OFF_SPICK + MAXDET * 8)      // 29024
#define OFF_CKEY  8192                            // phase E overlays dead sbox
#define OFF_CCLS  (OFF_CKEY + CCAP * 8)           // 16384 (dead sboxs region)

extern __shared__ unsigned char dsm[];

__global__ __launch_bounds__(512, 2) void yolo_fused_kernel(
        const float* __restrict__ pred,
        const int* __restrict__ p_oh,
        const int* __restrict__ p_ow,
        float* __restrict__ out) {
    __shared__ float s_r, s_dw, s_dh, s_xmax, s_ymax;
    __shared__ int  s_npick, s_T;
    __shared__ bool amLast;
    __shared__ unsigned int super[64];

    int tid  = threadIdx.x;
    int wid  = tid >> 5;
    int lane = tid & 31;
    int c    = blockIdx.x;

    // ---- phase A: decode (warp per box, full chip) ----
    if (tid == 0) {
        int oh = p_oh[0], ow = p_ow[0];
        double rw = INPUT_SZ / (double)ow;
        double rh = INPUT_SZ / (double)oh;
        double rr = rw < rh ? rw : rh;
        s_r    = (float)rr;
        s_dw   = (float)((INPUT_SZ - rr * (double)ow) * 0.5);
        s_dh   = (float)((INPUT_SZ - rr * (double)oh) * 0.5);
        s_xmax = (float)(ow - 1);
        s_ymax = (float)(oh - 1);
    }
    __syncthreads();

    for (int box = c * NWARP + wid; box < NBOX; box += GWARPS) {
        const float* p = pred + box * 85;

        // Per-lane argmax keeps the EARLIEST class achieving the lane max.
        float best = -1.0f;
        int bestc = 0;
        for (int cl = lane; cl < NCLS; cl += 32) {
            float v = p[5 + cl];
            if (v > best) { best = v; bestc = cl; }
        }
        // Cross-lane: max score bits (non-negative floats monotone), then min
        // class among lanes holding the max -> exact jnp.argmax semantics.
        unsigned int sb = __float_as_uint(best);
        unsigned int m  = __reduce_max_sync(0xffffffffu, sb);
        unsigned int cand = (sb == m) ? (unsigned int)bestc : 0xffffffffu;
        unsigned int minc = __reduce_min_sync(0xffffffffu, cand);
        if (lane) continue;
        best  = __uint_as_float(m);
        bestc = (int)minc;

        float r = s_r, dw = s_dw, dh = s_dh;
        float cx = p[0], cy = p[1], w = p[2], h = p[3], conf = p[4];
        float x1 = (cx - w * 0.5f - dw) / r;
        float y1 = (cy - h * 0.5f - dh) / r;
        float x2 = (cx + w * 0.5f - dw) / r;
        float y2 = (cy + h * 0.5f - dh) / r;
        x1 = fmaxf(x1, 0.0f);
        y1 = fmaxf(y1, 0.0f);
        x2 = fminf(x2, s_xmax);
        y2 = fminf(y2, s_ymax);
        if (x1 > x2 || y1 > y2) { x1 = y1 = x2 = y2 = 0.0f; }

        float area  = (x2 - x1) * (y2 - y1);
        float score = conf * best;
        if (!(area > 0.0f && score > SCORE_THR)) continue;

        int slot = atomicAdd(&g_cnt[bestc], 1);
        if (slot < MAXPER) {
            g_bbox[bestc * MAXPER + slot] = make_float4(x1, y1, x2, y2);
            // key: score (desc) > orig index (asc via NBOX-box) > slot (10b).
            g_bkey[bestc * MAXPER + slot] =
                ((unsigned long long)__float_as_uint(score) << 32) |
                ((unsigned long long)(NBOX - box) << 10) |
                (unsigned long long)(slot & 1023);
        }
    }

    // Non-NMS blocks zero `out` BEFORE arriving at barrier-1.
    if (c >= NCLS) {
        for (int j = (c - NCLS) * 512 + tid; j < MAXDET * 6; j += 208 * 512)
            out[j] = 0.0f;
    }

    // ---- phase B: barrier-1 ----
    __syncthreads();
    __threadfence();
    if (tid == 0) {
        atomicAdd(&g_bar1, 1u);
        if (c < NCLS)
            while (*(volatile unsigned int*)&g_bar1 < GRID) __nanosleep(32);
    }
    __syncthreads();
    if (c >= NCLS) return;

    // ---- phase C: per-class NMS (block c = class c) ----
    unsigned long long* skey  = (unsigned long long*)dsm;
    unsigned long long* skey2 = (unsigned long long*)(dsm + OFF_SKEY2);
    float4*             sbox  = (float4*)(dsm + OFF_SBOX);
    float4*             sboxs = (float4*)(dsm + OFF_SBOXS);
    unsigned int*       srow  = (unsigned int*)(dsm + OFF_SROW);
    unsigned long long* spick = (unsigned long long*)(dsm + OFF_SPICK);

    int n = g_cnt[c];
    if (n > MAXPER) n = MAXPER;
    if (tid == 0) {
        g_cnt[c] = 0;                       // restore invariant for next replay
        s_npick = 0;
    }
    __syncthreads();

    if (n > 0) {
        for (int j = tid; j < n; j += 512) {
            skey[j] = g_bkey[c * MAXPER + j];
            sbox[j] = g_bbox[c * MAXPER + j];
        }
        __syncthreads();

        // Counting sort descending (keys unique -> ranks unique in [0,n)),
        // with the box permutation fused in: slot field of skey[i] is i, so
        // sbox[i] belongs exactly to key skey[i].
        for (int i = tid; i < n; i += 512) {
            unsigned long long ki = skey[i];
            int rank = 0;
            #pragma unroll 4
            for (int j = 0; j < n; j++) rank += (skey[j] > ki);
            skey2[rank] = ki;
            sboxs[rank] = sbox[i];
        }
        __syncthreads();

        if (n <= NMAX) {
            // Suppression matrix, fixed stride WMAX: bit j of row i (j<i).
            int W = (n + 31) >> 5;
            for (int t = tid; t < n * W; t += 512) {
                int i = t / W, w = t % W;
                float4 bi = sboxs[i];
                float ai = (bi.z - bi.x) * (bi.w - bi.y);
                unsigned int bits = 0;
                int jend = min(i, (w + 1) * 32);
                for (int j = w * 32; j < jend; j++) {
                    float4 bj = sboxs[j];
                    float iw = fminf(bi.z, bj.z) - fmaxf(bi.x, bj.x);
                    float ih = fminf(bi.w, bj.w) - fmaxf(bi.y, bj.y);
                    iw = fmaxf(iw, 0.0f);
                    ih = fmaxf(ih, 0.0f);
                    float inter = iw * ih;
                    float uni = ai + (bj.z - bj.x) * (bj.w - bj.y) - inter;
                    // uni > 0 (bucketed boxes have area > 0): mul == div form
                    if (inter > IOU_THR * uni) bits |= 1u << (j & 31);
                }
                srow[i * WMAX + w] = bits;
            }
            __syncthreads();
            // Serial scan, kept-mask in registers, SOFTWARE-PIPELINED: the
            // row loads are independent of the kept state, so row i+1 is
            // prefetched while row i is tested. npick <= n <= 256 < MAXDET,
            // so no pick-count break is needed. The one-past prefetch at
            // i == n-1 stays inside the dynamic smem allocation.
            if (tid == 0) {
                const uint4* rowp = (const uint4*)(dsm + OFF_SROW);
                uint4 k0 = make_uint4(0, 0, 0, 0);
                uint4 k1 = make_uint4(0, 0, 0, 0);
                uint4 r0 = rowp[0];
                uint4 r1 = rowp[1];
                int npick = 0;
                for (int i = 0; i < n; i++) {
                    uint4 n0 = rowp[(i + 1) * 2];
                    uint4 n1 = rowp[(i + 1) * 2 + 1];
                    unsigned int sup =
                        (r0.x & k0.x) | (r0.y & k0.y) | (r0.z & k0.z) | (r0.w & k0.w) |
                        (r1.x & k1.x) | (r1.y & k1.y) | (r1.z & k1.z) | (r1.w & k1.w);
                    if (!sup) {
                        unsigned int b = 1u << (i & 31);
                        switch (i >> 5) {
                            case 0: k0.x |= b; break;
                            case 1: k0.y |= b; break;
                            case 2: k0.z |= b; break;
                            case 3: k0.w |= b; break;
                            case 4: k1.x |= b; break;
                            case 5: k1.y |= b; break;
                            case 6: k1.z |= b; break;
                            default: k1.w |= b; break;
                        }
                        spick[npick++] = skey2[i];
                    }
                    r0 = n0;
                    r1 = n1;
                }
                s_npick = npick;
            }
        } else {
            // Fallback (NMAX < n <= MAXPER, statistically untaken): warp-0 scan.
            if (tid < 32) {
                unsigned short* skept = (unsigned short*)srow;
                int m2 = 0, npick = 0;
                for (int i = 0; i < n && npick < MAXDET; i++) {
                    float4 b = sboxs[i];
                    float ab = (b.z - b.x) * (b.w - b.y);
                    bool sup = false;
                    for (int j0 = 0; j0 < m2; j0 += 32) {
                        bool pr = false;
                        int j = j0 + lane;
                        if (j < m2) {
                            float4 kb = sboxs[skept[j]];
                            float iw = fminf(b.z, kb.z) - fmaxf(b.x, kb.x);
                            float ih = fminf(b.w, kb.w) - fmaxf(b.y, kb.y);
                            iw = fmaxf(iw, 0.0f);
                            ih = fmaxf(ih, 0.0f);
                            float inter = iw * ih;
                            float uni = ab + (kb.z - kb.x) * (kb.w - kb.y) - inter;
                            pr = (inter > IOU_THR * uni);
                        }
                        if (__any_sync(0xffffffffu, pr)) { sup = true; break; }
                    }
                    if (!sup) {
                        if (lane == 0) {
                            skept[m2] = (unsigned short)i;   // sorted index
                            spick[npick] = skey2[i];
                        }
                        __syncwarp();
                        m2++; npick++;
                    }
                }
                if (lane == 0) s_npick = npick;
            }
        }
        __syncthreads();

        // Histogram this block's picks (scores in (0.3,1] -> bin in [0,1848)).
        int npick = s_npick;
        for (int j = tid; j < npick; j += 512) {
            unsigned int sb2 = (unsigned int)(spick[j] >> 32);
            atomicAdd(&g_hist[(sb2 - 0x3E990000u) >> 13], 1u);
        }
    }

    // ---- phase D: barrier-2, per-block threshold, candidate append ----
    __syncthreads();
    __threadfence();
    if (tid == 0) {
        atomicAdd(&g_bar2, 1u);
        while (*(volatile unsigned int*)&g_bar2 < NCLS) __nanosleep(32);
    }
    __syncthreads();

    // Every block computes the same T from the completed global histogram.
    unsigned int* sh = (unsigned int*)dsm;          // overlays dead skey/skey2
    for (int j = tid; j < NBIN; j += 512) sh[j] = g_hist[j];
    __syncthreads();
    if (tid < 64) {
        unsigned int s = 0;
        for (int w = 0; w < 32; w++) s += sh[tid * 32 + w];
        super[tid] = s;
    }
    __syncthreads();
    if (tid == 0) {
        int cum = 0, T = 0;
        int sb2 = 63;
        for (; sb2 >= 0; sb2--) {
            if (cum + (int)super[sb2] >= MAXDET) break;
            cum += (int)super[sb2];
        }
        if (sb2 >= 0) {
            int b = sb2 * 32 + 31;
            for (; b >= sb2 * 32; b--) {
                cum += (int)sh[b];
                if (cum >= MAXDET) break;
            }
            T = (b < sb2 * 32) ? sb2 * 32 : b;
        }
        s_T = T;                            // T==0 when total<300: all picks
    }
    __syncthreads();

    int T = s_T;
    int npick = s_npick;
    for (int j = tid; j < npick; j += 512) {
        unsigned long long k = spick[j];
        int b = (int)(((unsigned int)(k >> 32) - 0x3E990000u) >> 13);
        if (b >= T) {
            int idx = atomicAdd(&g_ccnt, 1);
            if (idx < CCAP) { g_ckey[idx] = k; g_ccls[idx] = (unsigned char)c; }
        }
    }

    // ---- phase E: last block ranks candidates and scatters ----
    // RACE FIX (R14): all threads finish appends BEFORE the block arrives on
    // g_done; every thread fences so data+count are globally visible first.
    __syncthreads();
    __threadfence();
    if (tid == 0)
        amLast = (atomicInc(&g_done, NCLS - 1) == NCLS - 1);  // auto-resets
    __syncthreads();
    if (!amLast) return;

    unsigned long long* ckey = (unsigned long long*)(dsm + OFF_CKEY);
    unsigned char*      ccls = (unsigned char*)(dsm + OFF_CCLS);
    __shared__ int s_C;

    if (tid == 0) {
        int C = g_ccnt;
        s_C = (C > CCAP) ? CCAP : C;
        g_ccnt = 0;                         // restore invariants
        g_bar1 = 0;
        g_bar2 = 0;
    }
    for (int j = tid; j < NBIN; j += 512) g_hist[j] = 0;
    __syncthreads();

    int C = s_C;
    for (int j = tid; j < C; j += 512) {
        ckey[j] = g_ckey[j];
        ccls[j] = g_ccls[j];
    }
    __syncthreads();

    for (int t = tid; t < C; t += 512) {
        unsigned long long mk = ckey[t];
        int rank = 0;
        #pragma unroll 4
        for (int j = 0; j < C; j++) rank += (ckey[j] > mk);
        if (rank < MAXDET) {
            int cls  = ccls[t];
            int slot = (int)(mk & 1023u);
            float4 b = g_bbox[cls * MAXPER + slot];
            float* row = out + rank * 6;
            row[0] = b.x; row[1] = b.y; row[2] = b.z; row[3] = b.w;
            row[4] = __uint_as_float((unsigned int)(mk >> 32));
            row[5] = (float)cls;
        }
    }
}

// ---------------------------------------------------------------------------
extern "C" void kernel_launch(void* const* d_in, const int* in_sizes, int n_in,
                              void* d_out, int out_size) {
    const float* pred = (const float*)d_in[0];
    const int*   oh   = (const int*)d_in[1];
    const int*   ow   = (const int*)d_in[2];
    float*       out  = (float*)d_out;

    cudaFuncSetAttribute(yolo_fused_kernel,
                         cudaFuncAttributeMaxDynamicSharedMemorySize,
                         DSMEM_BYTES);

    yolo_fused_kernel<<<GRID, 512, DSMEM_BYTES>>>(pred, oh, ow, out);
}